// round 13
// baseline (speedup 1.0000x reference)
#include <cuda_runtime.h>
#include <math.h>

// DeepLK inverse-compositional LK homography solve — single persistent kernel.
// img, temp: [8,1,512,512] f32. Output: p [8,8,1] then H [8,3,3] = 136 floats.
//
// Phase 0 fuses the Gram matrix J^T J with the iteration-0 residual J^T r:
// at p=0 the warp is identity, so the bilinear sample is exactly v = I[y,x].
// Only 9 full bilinear passes remain (iterations 1..9).
//
// R11: __launch_bounds__(256, 5) caps regs at 51 -> 5 CTAs/SM (40 warps vs 32),
// confining any spills to the one-shot phase-0 Gram accumulation.

#define WI 512
#define HI 512
#define NPIX (WI*HI)
#define NQUAD (NPIX/4)          // 65536 quads per batch
#define NB 8
#define NBLK 74                 // blocks per batch; grid (74,8)=592 <= 148*5=740
#define NTHR 256
#define NITER 10

__device__ float        g_partR[NB][NBLK][8];
__device__ float        g_partH[NB][NBLK][36];
__device__ unsigned int g_sem[NB];

__global__ void kZero() { if (threadIdx.x < NB) g_sem[threadIdx.x] = 0u; }

// per-batch software barrier: cumulative arrivals; all blocks poll the counter
__device__ __forceinline__ void batch_barrier(int b, unsigned target) {
    __threadfence();
    __syncthreads();
    if (threadIdx.x == 0) {
        atomicAdd(&g_sem[b], 1u);
        while (*(volatile unsigned int*)&g_sem[b] < target) __nanosleep(64);
    }
    __syncthreads();
}

__global__ void __launch_bounds__(NTHR, 5)
kPersist(const float* __restrict__ img, const float* __restrict__ temp,
         float* __restrict__ out, int out_size) {
    int b = blockIdx.y;
    const float* I = img  + (size_t)b * NPIX;
    const float* T = temp + (size_t)b * NPIX;
    int tid = threadIdx.x;
    int wid = tid >> 5, lane = tid & 31;
    unsigned FULL = 0xffffffffu;

    // contiguous quad range for this CTA (885 or 886 quads, balanced)
    int qstart = (int)(((long long)blockIdx.x * NQUAD) / NBLK);
    int qend   = (int)(((long long)(blockIdx.x + 1) * NQUAD) / NBLK);
    int qcnt   = qend - qstart;

    __shared__ double sH[36];
    __shared__ double sA[8][16];
    __shared__ double sInv[8][8];
    __shared__ double sv[8];
    __shared__ float  sp[8], sdp[8];
    __shared__ float  swp[8][8];
    __shared__ float  swh[8][36];

    const float BND = 0.99609375f;        // 1 - 2/512 exactly
    const float INVH = 1.0f / 255.5f;

    // =======================================================================
    // Phase 0: Gram partials Hm = J^T J (36) fused with J^T r at p = 0 (8).
    // At p=0: Xw = x, Yw = y exactly -> v = I[y,x]; no gathers needed.
    // =======================================================================
    {
        float acc[36];
#pragma unroll
        for (int c = 0; c < 36; c++) acc[c] = 0.0f;
        float accR[8];
#pragma unroll
        for (int c = 0; c < 8; c++) accR[c] = 0.0f;

        for (int qi = tid; qi < qcnt; qi += NTHR) {
            int q = qstart + qi;
            int i = q << 2;
            int x = i & (WI - 1), y = i >> 9;
            float Yc = (float)y - 255.5f;
            float4 Tc = *reinterpret_cast<const float4*>(T + i);
            float4 Ic = *reinterpret_cast<const float4*>(I + i);
            int yU = y > 0      ? y - 1 : 0;
            int yD = y < HI - 1 ? y + 1 : HI - 1;
            float4 TU = *reinterpret_cast<const float4*>(T + yU * WI + x);
            float4 TD = *reinterpret_cast<const float4*>(T + yD * WI + x);
            float Tm1 = (x > 0)      ? __ldg(T + i - 1) : Tc.x;
            float Tp4 = (x < WI - 4) ? __ldg(T + i + 4) : Tc.w;

            float Tca[4] = {Tc.x, Tc.y, Tc.z, Tc.w};
            float Ica[4] = {Ic.x, Ic.y, Ic.z, Ic.w};
            float gxa[4] = {0.5f * (Tc.y - Tm1), 0.5f * (Tc.z - Tc.x),
                            0.5f * (Tc.w - Tc.y), 0.5f * (Tp4 - Tc.z)};
            float gya[4] = {0.5f * (TD.x - TU.x), 0.5f * (TD.y - TU.y),
                            0.5f * (TD.z - TU.z), 0.5f * (TD.w - TU.w)};

            // iteration-0 mask per pixel (Xw = x, Yw = y exactly)
            float yn0 = (float)y * INVH - 1.0f;
            bool yok = (yn0 > -BND) && (yn0 < BND);

#pragma unroll
            for (int j = 0; j < 4; j++) {
                float X = (float)(x + j) - 255.5f;
                float gx = gxa[j], gy = gya[j];
                float s = X * gx + Yc * gy;
                float a[8];
                a[0] = X * gx; a[1] = Yc * gx; a[2] = gx;
                a[3] = X * gy; a[4] = Yc * gy; a[5] = gy;
                a[6] = -X * s; a[7] = -Yc * s;
                int c = 0;
#pragma unroll
                for (int ii = 0; ii < 8; ii++)
#pragma unroll
                    for (int jj = ii; jj < 8; jj++)
                        acc[c++] += a[ii] * a[jj];

                // it-0 residual: v = I exactly; mask via same formula
                float xn = (float)(x + j) * INVH - 1.0f;
                float mask = (xn > -BND && xn < BND && yok) ? 1.0f : 0.0f;
                float r = Ica[j] - Tca[j] * mask;
#pragma unroll
                for (int ii = 0; ii < 8; ii++)
                    accR[ii] += a[ii] * r;
            }
        }

#pragma unroll
        for (int c = 0; c < 36; c++)
            for (int off = 16; off > 0; off >>= 1)
                acc[c] += __shfl_down_sync(FULL, acc[c], off);
#pragma unroll
        for (int c = 0; c < 8; c++)
            for (int off = 16; off > 0; off >>= 1)
                accR[c] += __shfl_down_sync(FULL, accR[c], off);

        if (lane == 0) {
#pragma unroll
            for (int c = 0; c < 36; c++) swh[wid][c] = acc[c];
#pragma unroll
            for (int c = 0; c < 8; c++) swp[wid][c] = accR[c];
        }
        __syncthreads();
        if (tid < 36) {
            float s = 0.0f;
#pragma unroll
            for (int w = 0; w < 8; w++) s += swh[w][tid];
            g_partH[b][blockIdx.x][tid] = s;
        }
        if (tid < 8) {
            float s = 0.0f;
#pragma unroll
            for (int w = 0; w < 8; w++) s += swp[w][tid];
            g_partR[b][blockIdx.x][tid] = s;
        }
    }

    batch_barrier(b, NBLK);

    // every block redundantly (deterministically) reduces + inverts
    if (tid < 36) {
        double s = 0.0;
        for (int i = 0; i < NBLK; i++) s += (double)__ldcg(&g_partH[b][i][tid]);
        sH[tid] = s;
    }
    if (tid < 8) { sp[tid] = 0.0f; sdp[tid] = 1.0f; }
    __syncthreads();
    if (tid == 0) {
        int c = 0;
        for (int i = 0; i < 8; i++)
            for (int j = i; j < 8; j++) { sA[i][j] = sH[c]; sA[j][i] = sH[c]; c++; }
        for (int i = 0; i < 8; i++)
            for (int j = 0; j < 8; j++) sA[i][8 + j] = (i == j) ? 1.0 : 0.0;
        for (int col = 0; col < 8; col++) {
            int piv = col; double mx = fabs(sA[col][col]);
            for (int r = col + 1; r < 8; r++) {
                double v = fabs(sA[r][col]);
                if (v > mx) { mx = v; piv = r; }
            }
            if (piv != col)
                for (int j = 0; j < 16; j++) {
                    double tmp = sA[col][j]; sA[col][j] = sA[piv][j]; sA[piv][j] = tmp;
                }
            double inv = 1.0 / sA[col][col];
            for (int j = 0; j < 16; j++) sA[col][j] *= inv;
            for (int r = 0; r < 8; r++)
                if (r != col) {
                    double f = sA[r][col];
                    for (int j = 0; j < 16; j++) sA[r][j] -= f * sA[col][j];
                }
        }
        for (int i = 0; i < 8; i++)
            for (int j = 0; j < 8; j++) sInv[i][j] = sA[i][8 + j];
    }
    __syncthreads();

    // =======================================================================
    // Updates + remaining bilinear iterations.
    // it = 0 uses the phase-0 partials; it = 1..9 run full bilinear passes.
    // =======================================================================
    for (int it = 0; it < NITER; it++) {
        if (it > 0) {
            float p0 = sp[0], p1 = sp[1], p2 = sp[2];
            float p3 = sp[3], p4 = sp[4], p5 = sp[5];
            // p6 = p7 = 0 exactly (reference zeroes dp[6:8]); den == 1
            float A0 = 1.0f + p0, A1 = p3;
            float B0 = p1, B1 = 1.0f + p4;
            float C0 = p2 + 255.5f, C1 = p5 + 255.5f;

            float acc0 = 0.f, acc1 = 0.f, acc2 = 0.f, acc3 = 0.f;
            float acc4 = 0.f, acc5 = 0.f, acc6 = 0.f, acc7 = 0.f;

            for (int qi = tid; qi < qcnt; qi += NTHR) {
                int q = qstart + qi;
                int i = q << 2;
                int x = i & (WI - 1), y = i >> 9;
                float Yc = (float)y - 255.5f;

                float4 Tc = *reinterpret_cast<const float4*>(T + i);
                int yU = y > 0      ? y - 1 : 0;
                int yD = y < HI - 1 ? y + 1 : HI - 1;
                float4 TU = *reinterpret_cast<const float4*>(T + yU * WI + x);
                float4 TD = *reinterpret_cast<const float4*>(T + yD * WI + x);
                float Tm1 = (x > 0)      ? __ldg(T + i - 1) : Tc.x;
                float Tp4 = (x < WI - 4) ? __ldg(T + i + 4) : Tc.w;

                float Tca[4] = {Tc.x, Tc.y, Tc.z, Tc.w};
                float gxa[4] = {0.5f * (Tc.y - Tm1), 0.5f * (Tc.z - Tc.x),
                                0.5f * (Tc.w - Tc.y), 0.5f * (Tp4 - Tc.z)};
                float gya[4] = {0.5f * (TD.x - TU.x), 0.5f * (TD.y - TU.y),
                                0.5f * (TD.z - TU.z), 0.5f * (TD.w - TU.w)};

                float WBx = fmaf(Yc, B0, C0);          // per-quad hoist
                float WBy = fmaf(Yc, B1, C1);

#pragma unroll
                for (int j = 0; j < 4; j++) {
                    float X = (float)(x + j) - 255.5f;
                    float Xw = fmaf(X, A0, WBx);
                    float Yw = fmaf(X, A1, WBy);

                    // --- branchless bilinear sample, zeros padding ---
                    float x0f = floorf(Xw), y0f = floorf(Yw);
                    float wx = Xw - x0f, wy = Yw - y0f;
                    int x0 = (int)fminf(fmaxf(x0f, -2.0f), 513.0f);
                    int y0 = (int)fminf(fmaxf(y0f, -2.0f), 513.0f);
                    bool fx0 = (x0 >= 0 ) && (x0 <  WI    );
                    bool fx1 = (x0 >= -1) && (x0 <  WI - 1);
                    bool fy0 = (y0 >= 0 ) && (y0 <  HI    );
                    bool fy1 = (y0 >= -1) && (y0 <  HI - 1);
                    int xi0 = min(max(x0, 0), WI - 1), xi1 = min(max(x0 + 1, 0), WI - 1);
                    int yi0 = min(max(y0, 0), HI - 1), yi1 = min(max(y0 + 1, 0), HI - 1);

                    const float* r0 = I + yi0 * WI;
                    const float* r1 = I + yi1 * WI;
                    float v00 = __ldg(r0 + xi0);
                    float v10 = __ldg(r0 + xi1);
                    float v01 = __ldg(r1 + xi0);
                    float v11 = __ldg(r1 + xi1);

                    // validity folded into 1-D weight factors (bit-identical:
                    // products with exact 0/1 flags commute with rounding)
                    float wx0 = fx0 ? (1.0f - wx) : 0.0f;
                    float wx1 = fx1 ? wx          : 0.0f;
                    float wy0 = fy0 ? (1.0f - wy) : 0.0f;
                    float wy1 = fy1 ? wy          : 0.0f;

                    float v = 0.0f;
                    v += v00 * (wx0 * wy0);
                    v += v10 * (wx1 * wy0);
                    v += v01 * (wx0 * wy1);
                    v += v11 * (wx1 * wy1);

                    float xn = Xw * INVH - 1.0f;
                    float yn = Yw * INVH - 1.0f;
                    float mask = (xn > -BND && xn < BND &&
                                  yn > -BND && yn < BND) ? 1.0f : 0.0f;

                    float r = v - Tca[j] * mask;
                    float gr_x = gxa[j] * r;
                    float gr_y = gya[j] * r;
                    float t = X * gr_x + Yc * gr_y;

                    acc0 = fmaf(X,  gr_x, acc0);
                    acc1 = fmaf(Yc, gr_x, acc1);
                    acc2 += gr_x;
                    acc3 = fmaf(X,  gr_y, acc3);
                    acc4 = fmaf(Yc, gr_y, acc4);
                    acc5 += gr_y;
                    acc6 = fmaf(X,  -t, acc6);
                    acc7 = fmaf(Yc, -t, acc7);
                }
            }

            float acc[8] = {acc0, acc1, acc2, acc3, acc4, acc5, acc6, acc7};

            // --- block tree reduction ---
#pragma unroll
            for (int c = 0; c < 8; c++)
                for (int off = 16; off > 0; off >>= 1)
                    acc[c] += __shfl_down_sync(FULL, acc[c], off);
            if (lane == 0)
#pragma unroll
                for (int c = 0; c < 8; c++) swp[wid][c] = acc[c];
            __syncthreads();
            if (tid < 8) {
                float s = 0.0f;
#pragma unroll
                for (int w = 0; w < 8; w++) s += swp[w][tid];
                g_partR[b][blockIdx.x][tid] = s;
            }

            batch_barrier(b, (unsigned)(NBLK * (it + 1)));
        }

        // every block redundantly reduces partials: warp w handles channel w
        if (wid < 8) {
            double s = 0.0;
            for (int i = lane; i < NBLK; i += 32)
                s += (double)__ldcg(&g_partR[b][i][wid]);
            for (int off = 16; off > 0; off >>= 1)
                s += __shfl_down_sync(FULL, s, off);
            if (lane == 0) sv[wid] = s;
        }
        __syncthreads();

        if (tid < 8) {
            int i = tid;
            double n2 = 0.0;
#pragma unroll
            for (int j = 0; j < 8; j++) { double d = (double)sdp[j]; n2 += d * d; }
            bool gate = sqrt(n2) > 1e-3;
            double d = 0.0;
#pragma unroll
            for (int j = 0; j < 8; j++) d += sInv[i][j] * sv[j];
            if (i >= 6) d = 0.0;                 // no projective update
            float dpf = gate ? (float)d : 0.0f;
            __syncwarp(0x000000ffu);             // norm reads done before writes
            sdp[i] = dpf;
            sp[i]  = sp[i] - dpf;
        }
        __syncthreads();
    }

    // output: p [B,8] then H [B,3,3], written by block x==0 of each batch
    if (blockIdx.x == 0) {
        if (tid < 8) {
            int idx = b * 8 + tid;
            if (idx < out_size) out[idx] = sp[tid];
        }
        if (tid < 9) {
            float m[9] = {1.0f + sp[0], sp[1], sp[2],
                          sp[3], 1.0f + sp[4], sp[5],
                          sp[6], sp[7], 1.0f};
            int idx = NB * 8 + b * 9 + tid;
            if (idx < out_size) out[idx] = m[tid];
        }
    }
}

extern "C" void kernel_launch(void* const* d_in, const int* in_sizes, int n_in,
                              void* d_out, int out_size) {
    const float* img  = (const float*)d_in[0];
    const float* temp = (const float*)d_in[1];
    float* out = (float*)d_out;

    kZero<<<1, 32>>>();
    kPersist<<<dim3(NBLK, NB), NTHR>>>(img, temp, out, out_size);
}

// round 14
// speedup vs baseline: 1.9809x; 1.9809x over previous
#include <cuda_runtime.h>
#include <math.h>

// DeepLK inverse-compositional LK homography solve — single persistent kernel.
// img, temp: [8,1,512,512] f32. Output: p [8,8,1] then H [8,3,3] = 136 floats.
//
// Phase 0 fuses the Gram matrix J^T J with the iteration-0 residual J^T r
// (at p=0 the warp is identity, v = I[y,x] exactly) AND stores the template
// gradients gx, gy to a global scratch. The 9 remaining bilinear passes read
// Tc/Gx/Gy as three coalesced LDG.128s — no edge loads, no gradient math.

#define WI 512
#define HI 512
#define NPIX (WI*HI)
#define NQUAD (NPIX/4)          // 65536 quads per batch
#define NB 8
#define NBLK 74                 // blocks per batch; grid (74,8)=592 = 148 SMs * 4
#define NTHR 256
#define NITER 10

__device__ float        g_partR[NB][NBLK][8];
__device__ float        g_partH[NB][NBLK][36];
__device__ unsigned int g_sem[NB];
__device__ float4       g_gx[NB][NQUAD];   // per-quad template x-gradients
__device__ float4       g_gy[NB][NQUAD];   // per-quad template y-gradients

__global__ void kZero() { if (threadIdx.x < NB) g_sem[threadIdx.x] = 0u; }

// per-batch software barrier: cumulative arrivals; all blocks poll the counter
__device__ __forceinline__ void batch_barrier(int b, unsigned target) {
    __threadfence();
    __syncthreads();
    if (threadIdx.x == 0) {
        atomicAdd(&g_sem[b], 1u);
        while (*(volatile unsigned int*)&g_sem[b] < target) __nanosleep(64);
    }
    __syncthreads();
}

__global__ void __launch_bounds__(NTHR, 4)
kPersist(const float* __restrict__ img, const float* __restrict__ temp,
         float* __restrict__ out, int out_size) {
    int b = blockIdx.y;
    const float* I = img  + (size_t)b * NPIX;
    const float* T = temp + (size_t)b * NPIX;
    int tid = threadIdx.x;
    int wid = tid >> 5, lane = tid & 31;
    unsigned FULL = 0xffffffffu;

    // contiguous quad range for this CTA (885 or 886 quads, balanced)
    int qstart = (int)(((long long)blockIdx.x * NQUAD) / NBLK);
    int qend   = (int)(((long long)(blockIdx.x + 1) * NQUAD) / NBLK);
    int qcnt   = qend - qstart;

    __shared__ double sH[36];
    __shared__ double sA[8][16];
    __shared__ double sInv[8][8];
    __shared__ double sv[8];
    __shared__ float  sp[8], sdp[8];
    __shared__ float  swp[8][8];
    __shared__ float  swh[8][36];

    const float BND = 0.99609375f;        // 1 - 2/512 exactly
    const float INVH = 1.0f / 255.5f;

    // =======================================================================
    // Phase 0: Gram partials (36) + it-0 residual J^T r (8) + gradient store.
    // At p=0: Xw = x, Yw = y exactly -> v = I[y,x]; no gathers needed.
    // =======================================================================
    {
        float acc[36];
#pragma unroll
        for (int c = 0; c < 36; c++) acc[c] = 0.0f;
        float accR[8];
#pragma unroll
        for (int c = 0; c < 8; c++) accR[c] = 0.0f;

        for (int qi = tid; qi < qcnt; qi += NTHR) {
            int q = qstart + qi;
            int i = q << 2;
            int x = i & (WI - 1), y = i >> 9;
            float Yc = (float)y - 255.5f;
            float4 Tc = *reinterpret_cast<const float4*>(T + i);
            float4 Ic = *reinterpret_cast<const float4*>(I + i);
            int yU = y > 0      ? y - 1 : 0;
            int yD = y < HI - 1 ? y + 1 : HI - 1;
            float4 TU = *reinterpret_cast<const float4*>(T + yU * WI + x);
            float4 TD = *reinterpret_cast<const float4*>(T + yD * WI + x);
            float Tm1 = (x > 0)      ? __ldg(T + i - 1) : Tc.x;
            float Tp4 = (x < WI - 4) ? __ldg(T + i + 4) : Tc.w;

            float Tca[4] = {Tc.x, Tc.y, Tc.z, Tc.w};
            float Ica[4] = {Ic.x, Ic.y, Ic.z, Ic.w};
            float gxa[4] = {0.5f * (Tc.y - Tm1), 0.5f * (Tc.z - Tc.x),
                            0.5f * (Tc.w - Tc.y), 0.5f * (Tp4 - Tc.z)};
            float gya[4] = {0.5f * (TD.x - TU.x), 0.5f * (TD.y - TU.y),
                            0.5f * (TD.z - TU.z), 0.5f * (TD.w - TU.w)};

            // store gradients for the 9 bilinear passes (this CTA re-reads
            // only its own quads — no cross-CTA visibility needed)
            g_gx[b][q] = make_float4(gxa[0], gxa[1], gxa[2], gxa[3]);
            g_gy[b][q] = make_float4(gya[0], gya[1], gya[2], gya[3]);

            // iteration-0 mask per pixel (Xw = x, Yw = y exactly)
            float yn0 = (float)y * INVH - 1.0f;
            bool yok = (yn0 > -BND) && (yn0 < BND);

#pragma unroll
            for (int j = 0; j < 4; j++) {
                float X = (float)(x + j) - 255.5f;
                float gx = gxa[j], gy = gya[j];
                float s = X * gx + Yc * gy;
                float a[8];
                a[0] = X * gx; a[1] = Yc * gx; a[2] = gx;
                a[3] = X * gy; a[4] = Yc * gy; a[5] = gy;
                a[6] = -X * s; a[7] = -Yc * s;
                int c = 0;
#pragma unroll
                for (int ii = 0; ii < 8; ii++)
#pragma unroll
                    for (int jj = ii; jj < 8; jj++)
                        acc[c++] += a[ii] * a[jj];

                // it-0 residual: v = I exactly; mask via same formula
                float xn = (float)(x + j) * INVH - 1.0f;
                float mask = (xn > -BND && xn < BND && yok) ? 1.0f : 0.0f;
                float r = Ica[j] - Tca[j] * mask;
#pragma unroll
                for (int ii = 0; ii < 8; ii++)
                    accR[ii] += a[ii] * r;
            }
        }

#pragma unroll
        for (int c = 0; c < 36; c++)
            for (int off = 16; off > 0; off >>= 1)
                acc[c] += __shfl_down_sync(FULL, acc[c], off);
#pragma unroll
        for (int c = 0; c < 8; c++)
            for (int off = 16; off > 0; off >>= 1)
                accR[c] += __shfl_down_sync(FULL, accR[c], off);

        if (lane == 0) {
#pragma unroll
            for (int c = 0; c < 36; c++) swh[wid][c] = acc[c];
#pragma unroll
            for (int c = 0; c < 8; c++) swp[wid][c] = accR[c];
        }
        __syncthreads();
        if (tid < 36) {
            float s = 0.0f;
#pragma unroll
            for (int w = 0; w < 8; w++) s += swh[w][tid];
            g_partH[b][blockIdx.x][tid] = s;
        }
        if (tid < 8) {
            float s = 0.0f;
#pragma unroll
            for (int w = 0; w < 8; w++) s += swp[w][tid];
            g_partR[b][blockIdx.x][tid] = s;
        }
    }

    batch_barrier(b, NBLK);

    // every block redundantly (deterministically) reduces + inverts
    if (tid < 36) {
        double s = 0.0;
        for (int i = 0; i < NBLK; i++) s += (double)__ldcg(&g_partH[b][i][tid]);
        sH[tid] = s;
    }
    if (tid < 8) { sp[tid] = 0.0f; sdp[tid] = 1.0f; }
    __syncthreads();
    if (tid == 0) {
        int c = 0;
        for (int i = 0; i < 8; i++)
            for (int j = i; j < 8; j++) { sA[i][j] = sH[c]; sA[j][i] = sH[c]; c++; }
        for (int i = 0; i < 8; i++)
            for (int j = 0; j < 8; j++) sA[i][8 + j] = (i == j) ? 1.0 : 0.0;
        for (int col = 0; col < 8; col++) {
            int piv = col; double mx = fabs(sA[col][col]);
            for (int r = col + 1; r < 8; r++) {
                double v = fabs(sA[r][col]);
                if (v > mx) { mx = v; piv = r; }
            }
            if (piv != col)
                for (int j = 0; j < 16; j++) {
                    double tmp = sA[col][j]; sA[col][j] = sA[piv][j]; sA[piv][j] = tmp;
                }
            double inv = 1.0 / sA[col][col];
            for (int j = 0; j < 16; j++) sA[col][j] *= inv;
            for (int r = 0; r < 8; r++)
                if (r != col) {
                    double f = sA[r][col];
                    for (int j = 0; j < 16; j++) sA[r][j] -= f * sA[col][j];
                }
        }
        for (int i = 0; i < 8; i++)
            for (int j = 0; j < 8; j++) sInv[i][j] = sA[i][8 + j];
    }
    __syncthreads();

    // =======================================================================
    // Updates + remaining bilinear iterations.
    // it = 0 uses the phase-0 partials; it = 1..9 run full bilinear passes.
    // =======================================================================
    for (int it = 0; it < NITER; it++) {
        if (it > 0) {
            float p0 = sp[0], p1 = sp[1], p2 = sp[2];
            float p3 = sp[3], p4 = sp[4], p5 = sp[5];
            // p6 = p7 = 0 exactly (reference zeroes dp[6:8]); den == 1
            float A0 = 1.0f + p0, A1 = p3;
            float B0 = p1, B1 = 1.0f + p4;
            float C0 = p2 + 255.5f, C1 = p5 + 255.5f;

            float acc0 = 0.f, acc1 = 0.f, acc2 = 0.f, acc3 = 0.f;
            float acc4 = 0.f, acc5 = 0.f, acc6 = 0.f, acc7 = 0.f;

            for (int qi = tid; qi < qcnt; qi += NTHR) {
                int q = qstart + qi;
                int i = q << 2;
                int x = i & (WI - 1), y = i >> 9;
                float Yc = (float)y - 255.5f;

                float4 Tc = *reinterpret_cast<const float4*>(T + i);
                float4 Gx = g_gx[b][q];
                float4 Gy = g_gy[b][q];

                float Tca[4] = {Tc.x, Tc.y, Tc.z, Tc.w};
                float gxa[4] = {Gx.x, Gx.y, Gx.z, Gx.w};
                float gya[4] = {Gy.x, Gy.y, Gy.z, Gy.w};

                float WBx = fmaf(Yc, B0, C0);          // per-quad hoist
                float WBy = fmaf(Yc, B1, C1);

#pragma unroll
                for (int j = 0; j < 4; j++) {
                    float X = (float)(x + j) - 255.5f;
                    float Xw = fmaf(X, A0, WBx);
                    float Yw = fmaf(X, A1, WBy);

                    // --- branchless bilinear sample, zeros padding ---
                    float x0f = floorf(Xw), y0f = floorf(Yw);
                    float wx = Xw - x0f, wy = Yw - y0f;
                    int x0 = (int)fminf(fmaxf(x0f, -2.0f), 513.0f);
                    int y0 = (int)fminf(fmaxf(y0f, -2.0f), 513.0f);
                    bool fx0 = (x0 >= 0 ) && (x0 <  WI    );
                    bool fx1 = (x0 >= -1) && (x0 <  WI - 1);
                    bool fy0 = (y0 >= 0 ) && (y0 <  HI    );
                    bool fy1 = (y0 >= -1) && (y0 <  HI - 1);
                    int xi0 = min(max(x0, 0), WI - 1), xi1 = min(max(x0 + 1, 0), WI - 1);
                    int yi0 = min(max(y0, 0), HI - 1), yi1 = min(max(y0 + 1, 0), HI - 1);

                    const float* r0 = I + yi0 * WI;
                    const float* r1 = I + yi1 * WI;
                    float v00 = __ldg(r0 + xi0);
                    float v10 = __ldg(r0 + xi1);
                    float v01 = __ldg(r1 + xi0);
                    float v11 = __ldg(r1 + xi1);

                    // validity folded into 1-D weight factors (bit-identical:
                    // products with exact 0/1 flags commute with rounding)
                    float wx0 = fx0 ? (1.0f - wx) : 0.0f;
                    float wx1 = fx1 ? wx          : 0.0f;
                    float wy0 = fy0 ? (1.0f - wy) : 0.0f;
                    float wy1 = fy1 ? wy          : 0.0f;

                    float v = 0.0f;
                    v += v00 * (wx0 * wy0);
                    v += v10 * (wx1 * wy0);
                    v += v01 * (wx0 * wy1);
                    v += v11 * (wx1 * wy1);

                    float xn = Xw * INVH - 1.0f;
                    float yn = Yw * INVH - 1.0f;
                    float mask = (xn > -BND && xn < BND &&
                                  yn > -BND && yn < BND) ? 1.0f : 0.0f;

                    float r = v - Tca[j] * mask;
                    float gr_x = gxa[j] * r;
                    float gr_y = gya[j] * r;
                    float t = X * gr_x + Yc * gr_y;

                    acc0 = fmaf(X,  gr_x, acc0);
                    acc1 = fmaf(Yc, gr_x, acc1);
                    acc2 += gr_x;
                    acc3 = fmaf(X,  gr_y, acc3);
                    acc4 = fmaf(Yc, gr_y, acc4);
                    acc5 += gr_y;
                    acc6 = fmaf(X,  -t, acc6);
                    acc7 = fmaf(Yc, -t, acc7);
                }
            }

            float acc[8] = {acc0, acc1, acc2, acc3, acc4, acc5, acc6, acc7};

            // --- block tree reduction ---
#pragma unroll
            for (int c = 0; c < 8; c++)
                for (int off = 16; off > 0; off >>= 1)
                    acc[c] += __shfl_down_sync(FULL, acc[c], off);
            if (lane == 0)
#pragma unroll
                for (int c = 0; c < 8; c++) swp[wid][c] = acc[c];
            __syncthreads();
            if (tid < 8) {
                float s = 0.0f;
#pragma unroll
                for (int w = 0; w < 8; w++) s += swp[w][tid];
                g_partR[b][blockIdx.x][tid] = s;
            }

            batch_barrier(b, (unsigned)(NBLK * (it + 1)));
        }

        // every block redundantly reduces partials: warp w handles channel w
        if (wid < 8) {
            double s = 0.0;
            for (int i = lane; i < NBLK; i += 32)
                s += (double)__ldcg(&g_partR[b][i][wid]);
            for (int off = 16; off > 0; off >>= 1)
                s += __shfl_down_sync(FULL, s, off);
            if (lane == 0) sv[wid] = s;
        }
        __syncthreads();

        if (tid < 8) {
            int i = tid;
            double n2 = 0.0;
#pragma unroll
            for (int j = 0; j < 8; j++) { double d = (double)sdp[j]; n2 += d * d; }
            bool gate = sqrt(n2) > 1e-3;
            double d = 0.0;
#pragma unroll
            for (int j = 0; j < 8; j++) d += sInv[i][j] * sv[j];
            if (i >= 6) d = 0.0;                 // no projective update
            float dpf = gate ? (float)d : 0.0f;
            __syncwarp(0x000000ffu);             // norm reads done before writes
            sdp[i] = dpf;
            sp[i]  = sp[i] - dpf;
        }
        __syncthreads();
    }

    // output: p [B,8] then H [B,3,3], written by block x==0 of each batch
    if (blockIdx.x == 0) {
        if (tid < 8) {
            int idx = b * 8 + tid;
            if (idx < out_size) out[idx] = sp[tid];
        }
        if (tid < 9) {
            float m[9] = {1.0f + sp[0], sp[1], sp[2],
                          sp[3], 1.0f + sp[4], sp[5],
                          sp[6], sp[7], 1.0f};
            int idx = NB * 8 + b * 9 + tid;
            if (idx < out_size) out[idx] = m[tid];
        }
    }
}

extern "C" void kernel_launch(void* const* d_in, const int* in_sizes, int n_in,
                              void* d_out, int out_size) {
    const float* img  = (const float*)d_in[0];
    const float* temp = (const float*)d_in[1];
    float* out = (float*)d_out;

    kZero<<<1, 32>>>();
    kPersist<<<dim3(NBLK, NB), NTHR>>>(img, temp, out, out_size);
}